// round 7
// baseline (speedup 1.0000x reference)
#include <cuda_runtime.h>
#include <math.h>

// Problem constants
#define BATCH   4
#define CHANS   64
#define NBC     256                 // BATCH * CHANS
#define SPATIAL 524288              // 32*128*128 elements per (b,c)
#define SPAT4   131072              // SPATIAL / 4 (float4)
#define NBLK    512                 // persistent blocks (2 per bc) — all co-resident
#define PARTS   2                   // partial blocks per bc
#define CHUNK4  65536               // float4 per block (1 MiB)
#define ITERS   256                 // CHUNK4 / 256 threads
#define REDR    4                   // C // R = 64/16

// Deterministic scratch (no device allocation allowed)
__device__ float g_part_s [NBLK];
__device__ float g_part_ss[NBLK];
__device__ float g_gate   [NBC];
__device__ unsigned int g_arrive;   // phase-1 completion counter (reset in-kernel)
__device__ unsigned int g_flag;     // gate-ready flag                (reset in-kernel)
__device__ unsigned int g_seen;     // barrier-exit counter           (reset in-kernel)

// ---------------------------------------------------------------------------
// Single persistent kernel: 512 blocks x 256 threads, all co-resident
// (launch_bounds(256,8) caps regs at 32 -> >=8 CTAs/SM >> 512/148).
// Phase 1: each block reduces its own contiguous 1 MiB chunk of x.
// Software grid barrier; last-arriving block computes the SE gate.
// Phase 2: each block rescales ITS OWN chunk in REVERSE order so the
// L2/L1-resident tail of its phase-1 reads is re-used before eviction.
// ---------------------------------------------------------------------------
__global__ __launch_bounds__(256, 8) void cca_fused_kernel(
    const float4* __restrict__ x, float4* __restrict__ out,
    const float*  __restrict__ w1, const float* __restrict__ b1,
    const float*  __restrict__ w2, const float* __restrict__ b2)
{
    const int bid = blockIdx.x;          // 0..NBLK-1
    const int tid = threadIdx.x;
    const int bc  = bid >> 1;            // chunk layout: bid*CHUNK4 == bc*SPAT4 + part*CHUNK4

    const size_t  base = (size_t)bid * CHUNK4;
    const float4* px   = x   + base;
    float4*       po   = out + base;

    // ---------------- Phase 1: block-local sum / sum-of-squares ----------------
    float s = 0.f, ss = 0.f;
    #pragma unroll 8
    for (int k = 0; k < ITERS; ++k) {
        float4 v = px[k * 256 + tid];
        s  += v.x + v.y + v.z + v.w;
        ss += v.x * v.x + v.y * v.y + v.z * v.z + v.w * v.w;
    }

    #pragma unroll
    for (int o = 16; o > 0; o >>= 1) {
        s  += __shfl_xor_sync(0xffffffffu, s,  o);
        ss += __shfl_xor_sync(0xffffffffu, ss, o);
    }

    __shared__ float sh_s[8], sh_ss[8];
    __shared__ bool  sh_last;
    const int w = tid >> 5;
    if ((tid & 31) == 0) { sh_s[w] = s; sh_ss[w] = ss; }
    __syncthreads();

    if (tid == 0) {
        float ts = 0.f, tss = 0.f;
        #pragma unroll
        for (int i = 0; i < 8; ++i) { ts += sh_s[i]; tss += sh_ss[i]; }
        g_part_s [bid] = ts;
        g_part_ss[bid] = tss;
        __threadfence();                                   // publish partials
        unsigned int prev = atomicAdd(&g_arrive, 1u);
        sh_last = (prev == NBLK - 1u);
    }
    __syncthreads();

    // ---------------- Grid barrier + SE gate (last block only) ----------------
    if (sh_last) {
        __threadfence();                                   // acquire all partials
        const int t = tid;                                 // t == bc index (256 threads)

        float fs  = g_part_s [2 * t] + g_part_s [2 * t + 1];
        float fss = g_part_ss[2 * t] + g_part_ss[2 * t + 1];
        const float invN = 1.0f / (float)SPATIAL;
        const float mean = fs * invN;
        const float var  = fmaxf(fss * invN - mean * mean, 0.f);
        const float stdv = sqrtf(var);

        __shared__ float y[NBC];
        y[t] = stdv + mean;
        __syncthreads();

        __shared__ float h[BATCH * REDR];
        if (t < BATCH * REDR) {
            const int b = t / REDR;
            const int r = t % REDR;
            float acc = b1[r];
            #pragma unroll
            for (int c = 0; c < CHANS; ++c)
                acc += w1[r * CHANS + c] * y[b * CHANS + c];
            h[t] = fmaxf(acc, 0.f);
        }
        __syncthreads();

        {
            const int b = t / CHANS;
            const int c = t % CHANS;
            float acc = b2[c];
            #pragma unroll
            for (int r = 0; r < REDR; ++r)
                acc += w2[c * REDR + r] * h[b * REDR + r];
            g_gate[t] = 1.0f / (1.0f + expf(-acc));
        }
        __syncthreads();
        if (tid == 0) {
            g_arrive = 0;                                  // all NBLK arrived; safe to reset
            __threadfence();                               // publish gates + reset
            atomicExch(&g_flag, 1u);                       // release the grid
        }
        __syncthreads();
    } else {
        if (tid == 0) {
            while (atomicAdd(&g_flag, 0u) == 0u) __nanosleep(64);
        }
        __syncthreads();
        __threadfence();                                   // acquire gates
    }

    // Barrier-exit bookkeeping: last block through resets the flag machinery.
    if (tid == 0) {
        unsigned int o = atomicAdd(&g_seen, 1u);
        if (o == NBLK - 1u) {                              // everyone is past the spin
            g_seen = 0;
            __threadfence();
            atomicExch(&g_flag, 0u);
        }
    }

    // ---------------- Phase 2: rescale own chunk, reverse order ----------------
    const float g = g_gate[bc];
    #pragma unroll 4
    for (int k = ITERS - 1; k >= 0; --k) {
        const int i = k * 256 + tid;
        float4 v = __ldcs(px + i);                         // tail hits L2/L1; misses fill evict-first
        v.x *= g; v.y *= g; v.z *= g; v.w *= g;
        __stcs(po + i, v);                                 // streaming store, don't pollute L2
    }
}

// ---------------------------------------------------------------------------
extern "C" void kernel_launch(void* const* d_in, const int* in_sizes, int n_in,
                              void* d_out, int out_size) {
    const float* x  = (const float*)d_in[0];   // [4,64,32,128,128]
    const float* w1 = (const float*)d_in[1];   // [4,64]
    const float* b1 = (const float*)d_in[2];   // [4]
    const float* w2 = (const float*)d_in[3];   // [64,4]
    const float* b2 = (const float*)d_in[4];   // [64]
    float* out = (float*)d_out;

    cca_fused_kernel<<<NBLK, 256>>>((const float4*)x, (float4*)out, w1, b1, w2, b2);
}

// round 8
// speedup vs baseline: 1.2376x; 1.2376x over previous
#include <cuda_runtime.h>
#include <math.h>

// Problem constants
#define BATCH   4
#define CHANS   64
#define NBC     256                 // BATCH * CHANS
#define SPATIAL 524288              // 32*128*128 elements per (b,c)
#define SPAT4   131072              // SPATIAL / 4 (float4)
#define PARTS   8                   // reduction blocks per (b,c)
#define REDR    4                   // C // R = 64/16
#define NRED    (NBC * PARTS)       // 2048 reduce blocks

// Deterministic scratch (no device allocation allowed)
__device__ float g_part_s [NBC * PARTS];
__device__ float g_part_ss[NBC * PARTS];
__device__ float g_gate   [NBC];
__device__ unsigned int g_done;     // zero-init; reset by the last block each call

// ---------------------------------------------------------------------------
// Kernel 1: per-(b,c) partial sum / sum-of-squares, SE MLP fused into the
// last-finishing block (threadfence-reduction pattern).
// grid = (PARTS, NBC) = 2048 blocks, block = 256 -> occ 8 CTA/SM, 86% DRAM.
// ---------------------------------------------------------------------------
__global__ __launch_bounds__(256) void cca_reduce_se_kernel(
    const float4* __restrict__ x,
    const float*  __restrict__ w1, const float* __restrict__ b1,
    const float*  __restrict__ w2, const float* __restrict__ b2)
{
    const int part = blockIdx.x;      // 0..PARTS-1
    const int bc   = blockIdx.y;      // 0..NBC-1
    const int tid  = threadIdx.x;

    const float4* p = x + (size_t)bc * SPAT4 + (size_t)part * (SPAT4 / PARTS);

    float s = 0.f, ss = 0.f;
    #pragma unroll 16
    for (int k = 0; k < 64; ++k) {
        float4 v = p[tid + k * 256];
        s  += v.x + v.y + v.z + v.w;
        ss += v.x * v.x + v.y * v.y + v.z * v.z + v.w * v.w;
    }

    // warp reduce
    #pragma unroll
    for (int o = 16; o > 0; o >>= 1) {
        s  += __shfl_xor_sync(0xffffffffu, s,  o);
        ss += __shfl_xor_sync(0xffffffffu, ss, o);
    }

    __shared__ float sh_s[8], sh_ss[8];
    __shared__ bool  sh_last;
    const int w = tid >> 5;
    if ((tid & 31) == 0) { sh_s[w] = s; sh_ss[w] = ss; }
    __syncthreads();

    if (tid == 0) {
        float ts = 0.f, tss = 0.f;
        #pragma unroll
        for (int i = 0; i < 8; ++i) { ts += sh_s[i]; tss += sh_ss[i]; }
        g_part_s [bc * PARTS + part] = ts;
        g_part_ss[bc * PARTS + part] = tss;
        __threadfence();                               // publish partials
        unsigned int prev = atomicAdd(&g_done, 1u);
        sh_last = (prev == NRED - 1u);
    }
    __syncthreads();
    if (!sh_last) return;

    // ---- Last block: finish reduction + SE MLP (thread t = bc index) ----
    __threadfence();                                   // acquire partials
    const int t = tid;

    float fs = 0.f, fss = 0.f;
    #pragma unroll
    for (int i = 0; i < PARTS; ++i) {
        fs  += g_part_s [t * PARTS + i];
        fss += g_part_ss[t * PARTS + i];
    }
    const float invN = 1.0f / (float)SPATIAL;
    const float mean = fs * invN;
    const float var  = fmaxf(fss * invN - mean * mean, 0.f);
    const float stdv = sqrtf(var);

    __shared__ float y[NBC];
    y[t] = stdv + mean;
    __syncthreads();

    __shared__ float h[BATCH * REDR];
    if (t < BATCH * REDR) {
        const int b = t / REDR;
        const int r = t % REDR;
        float acc = b1[r];
        #pragma unroll
        for (int c = 0; c < CHANS; ++c)
            acc += w1[r * CHANS + c] * y[b * CHANS + c];
        h[t] = fmaxf(acc, 0.f);
    }
    __syncthreads();

    const int b = t / CHANS;
    const int c = t % CHANS;
    float acc = b2[c];
    #pragma unroll
    for (int r = 0; r < REDR; ++r)
        acc += w2[c * REDR + r] * h[b * REDR + r];
    g_gate[t] = 1.0f / (1.0f + expf(-acc));

    if (t == 0) g_done = 0;                            // reset for next replay
    __threadfence();                                   // publish gate + reset
}

// ---------------------------------------------------------------------------
// Kernel 2: out = x * g[bc]. grid = (128, NBC), block = 256, 4 float4/thread,
// forward coalesced order (the R5 layout that measured 84.9% DRAM).
// Launched with PDL: cudaGridDependencySynchronize() returns only after ALL
// of kernel 1's writes (partials + gate) are visible -- semantics identical
// to a normal stream dependency, but the grid launch overlaps k1's tail.
// ---------------------------------------------------------------------------
__global__ __launch_bounds__(256) void cca_scale_kernel(const float4* __restrict__ x,
                                                        float4* __restrict__ out) {
    cudaGridDependencySynchronize();                   // wait for k1 completion

    const int bc = blockIdx.y;
    const float g = g_gate[bc];
    const size_t base = (size_t)bc * SPAT4;
    const int idx = blockIdx.x * 256 + threadIdx.x;    // 0..32767

    #pragma unroll
    for (int k = 0; k < 4; ++k) {
        const size_t i = base + idx + (size_t)k * (128 * 256);
        float4 v = x[i];
        v.x *= g; v.y *= g; v.z *= g; v.w *= g;
        out[i] = v;
    }
}

// ---------------------------------------------------------------------------
extern "C" void kernel_launch(void* const* d_in, const int* in_sizes, int n_in,
                              void* d_out, int out_size) {
    const float* x  = (const float*)d_in[0];   // [4,64,32,128,128]
    const float* w1 = (const float*)d_in[1];   // [4,64]
    const float* b1 = (const float*)d_in[2];   // [4]
    const float* w2 = (const float*)d_in[3];   // [64,4]
    const float* b2 = (const float*)d_in[4];   // [64]
    float* out = (float*)d_out;

    cca_reduce_se_kernel<<<dim3(PARTS, NBC), 256>>>((const float4*)x, w1, b1, w2, b2);

    // Scale kernel with programmatic dependent launch (overlap launch latency).
    cudaLaunchConfig_t cfg = {};
    cfg.gridDim  = dim3(128, NBC);
    cfg.blockDim = dim3(256);
    cfg.dynamicSmemBytes = 0;
    cfg.stream = 0;                                    // same (captured) stream
    cudaLaunchAttribute attrs[1];
    attrs[0].id = cudaLaunchAttributeProgrammaticStreamSerialization;
    attrs[0].val.programmaticStreamSerializationAllowed = 1;
    cfg.attrs = attrs;
    cfg.numAttrs = 1;
    cudaLaunchKernelEx(&cfg, cca_scale_kernel, (const float4*)x, (float4*)out);
}